// round 2
// baseline (speedup 1.0000x reference)
#include <cuda_runtime.h>
#include <cstdint>

typedef unsigned long long ull;

#define Bt   4
#define St   1024
#define HIDt 1024
#define NHt  16
#define HDt  64

__device__ float g_q[Bt * NHt * St * HDt];
__device__ float g_k[Bt * NHt * St * HDt];
__device__ float g_v[Bt * NHt * St * HDt];

__device__ __forceinline__ ull fma2(ull a, ull b, ull c) {
    ull d; asm("fma.rn.f32x2 %0, %1, %2, %3;" : "=l"(d) : "l"(a), "l"(b), "l"(c)); return d;
}
__device__ __forceinline__ ull mul2(ull a, ull b) {
    ull d; asm("mul.rn.f32x2 %0, %1, %2;" : "=l"(d) : "l"(a), "l"(b)); return d;
}
__device__ __forceinline__ ull f2u(float x, float y) {
    ull v; asm("mov.b64 %0, {%1, %2};" : "=l"(v) : "f"(x), "f"(y)); return v;
}
__device__ __forceinline__ float2 u2f(ull v) {
    float2 f; asm("mov.b64 {%0, %1}, %2;" : "=f"(f.x), "=f"(f.y) : "l"(v)); return f;
}
__device__ __forceinline__ void sts_dup(void* p, float v) {
    asm volatile("st.shared.v2.f32 [%0], {%1, %1};"
                 :: "l"((ull)__cvta_generic_to_shared(p)), "f"(v));
}

// ========================= QKV projection GEMM =============================
__global__ __launch_bounds__(256, 2)
void qkv_gemm(const float* __restrict__ X,
              const float* __restrict__ Wq, const float* __restrict__ bq,
              const float* __restrict__ Wk, const float* __restrict__ bk,
              const float* __restrict__ Wv, const float* __restrict__ bv)
{
    __shared__ __align__(16) ull   As2[16][128];
    __shared__ __align__(16) float Bs[16][128];

    const int tid = threadIdx.x;
    const int tx = tid & 15, ty = tid >> 4;
    const int bx = blockIdx.x, by = blockIdx.y, mz = blockIdx.z;

    const float* W    = (mz == 0) ? Wq : (mz == 1) ? Wk : Wv;
    const float* bias = (mz == 0) ? bq : (mz == 1) ? bk : bv;
    float*       dst  = (mz == 0) ? g_q : (mz == 1) ? g_k : g_v;

    const float* Ap = X + (size_t)by * 128 * HIDt;
    const float* Wp = W + (size_t)bx * 128 * HIDt;

    const int r0 = tid >> 2;
    const int r1 = r0 + 64;
    const int kq = (tid & 3) << 2;

    ull C2[8][4];
#pragma unroll
    for (int i = 0; i < 8; ++i)
#pragma unroll
        for (int j = 0; j < 4; ++j) C2[i][j] = 0ull;

    float4 a0 = *(const float4*)(Ap + (size_t)r0 * HIDt + kq);
    float4 a1 = *(const float4*)(Ap + (size_t)r1 * HIDt + kq);
    float4 w0 = *(const float4*)(Wp + (size_t)r0 * HIDt + kq);
    float4 w1 = *(const float4*)(Wp + (size_t)r1 * HIDt + kq);

    for (int kt = 0; kt < HIDt / 16; ++kt) {
        __syncthreads();
#pragma unroll
        for (int c = 0; c < 4; ++c) {
            sts_dup(&As2[kq + c][r0], ((const float*)&a0)[c]);
            sts_dup(&As2[kq + c][r1], ((const float*)&a1)[c]);
            Bs[kq + c][r0] = ((const float*)&w0)[c];
            Bs[kq + c][r1] = ((const float*)&w1)[c];
        }
        __syncthreads();
        if (kt < HIDt / 16 - 1) {
            const int k0 = (kt + 1) * 16;
            a0 = *(const float4*)(Ap + (size_t)r0 * HIDt + k0 + kq);
            a1 = *(const float4*)(Ap + (size_t)r1 * HIDt + k0 + kq);
            w0 = *(const float4*)(Wp + (size_t)r0 * HIDt + k0 + kq);
            w1 = *(const float4*)(Wp + (size_t)r1 * HIDt + k0 + kq);
        }
#pragma unroll
        for (int kk = 0; kk < 16; ++kk) {
            const ulonglong2* ar = (const ulonglong2*)&As2[kk][ty << 3];
            ulonglong2 a01 = ar[0], a23 = ar[1], a45 = ar[2], a67 = ar[3];
            float4 bl = *(const float4*)&Bs[kk][tx << 2];
            float4 bh = *(const float4*)&Bs[kk][64 + (tx << 2)];
            const ull bb0 = f2u(bl.x, bl.y), bb1 = f2u(bl.z, bl.w);
            const ull bb2 = f2u(bh.x, bh.y), bb3 = f2u(bh.z, bh.w);
            const ull aa[8] = {a01.x, a01.y, a23.x, a23.y, a45.x, a45.y, a67.x, a67.y};
#pragma unroll
            for (int i = 0; i < 8; ++i) {
                C2[i][0] = fma2(aa[i], bb0, C2[i][0]);
                C2[i][1] = fma2(aa[i], bb1, C2[i][1]);
                C2[i][2] = fma2(aa[i], bb2, C2[i][2]);
                C2[i][3] = fma2(aa[i], bb3, C2[i][3]);
            }
        }
    }

    const float4 bl4 = *(const float4*)(bias + bx * 128 + (tx << 2));
    const float4 bh4 = *(const float4*)(bias + bx * 128 + 64 + (tx << 2));
    const int h0 = bx * 2, h1 = bx * 2 + 1;
#pragma unroll
    for (int i = 0; i < 8; ++i) {
        const int m  = by * 128 + (ty << 3) + i;
        const int gb = m >> 10, s = m & 1023;
        float2 c0 = u2f(C2[i][0]), c1 = u2f(C2[i][1]);
        float2 c2 = u2f(C2[i][2]), c3 = u2f(C2[i][3]);
        float4 lo = make_float4(c0.x + bl4.x, c0.y + bl4.y, c1.x + bl4.z, c1.y + bl4.w);
        float4 hi = make_float4(c2.x + bh4.x, c2.y + bh4.y, c3.x + bh4.z, c3.y + bh4.w);
        *(float4*)(dst + (((size_t)gb * NHt + h0) * St + s) * HDt + (tx << 2)) = lo;
        *(float4*)(dst + (((size_t)gb * NHt + h1) * St + s) * HDt + (tx << 2)) = hi;
    }
}

// ========================= Flash attention (fp32) ==========================
#define ATTN_SMEM 98560

__global__ __launch_bounds__(256, 2)
void attn_kernel(const float* __restrict__ mask, float* __restrict__ out)
{
    extern __shared__ __align__(16) char smem_raw[];
    ull   (*Qs2)[64] = (ull (*)[64])(smem_raw);            // 32 KB dup(Q*scale)
    float (*Kst)[64] = (float (*)[64])(smem_raw + 32768);  // 16 KB K^T [d][key]
    float (*Vs)[64]  = (float (*)[64])(smem_raw + 49152);  // 16 KB [key][d]
    ull   (*Ps2)[64] = (ull (*)[64])(smem_raw + 65536);    // 32 KB dup(P)
    float* mbias     = (float*)(smem_raw + 98304);         // 256 B

    const int tid = threadIdx.x;
    const int tx = tid & 15, ty = tid >> 4;
    const int qt = blockIdx.x, h = blockIdx.y, b = blockIdx.z;

    const size_t bh_off = ((size_t)(b * NHt + h)) * St * HDt;
    const float* qb = g_q + bh_off + (size_t)qt * 64 * HDt;
    const float* kb = g_k + bh_off;
    const float* vb = g_v + bh_off;
    const float* mrow = mask + (size_t)b * St;

    const int lr = tid >> 2;
    const int lc = (tid & 3) << 4;

#pragma unroll
    for (int c = 0; c < 4; ++c) {
        float4 v = *(const float4*)(qb + (size_t)lr * HDt + lc + c * 4);
        sts_dup(&Qs2[lr][lc + c * 4 + 0], v.x * 0.125f);
        sts_dup(&Qs2[lr][lc + c * 4 + 1], v.y * 0.125f);
        sts_dup(&Qs2[lr][lc + c * 4 + 2], v.z * 0.125f);
        sts_dup(&Qs2[lr][lc + c * 4 + 3], v.w * 0.125f);
    }

    float m_i[4] = {-1e30f, -1e30f, -1e30f, -1e30f};
    float l_i[4] = {0.f, 0.f, 0.f, 0.f};
    ull O2[4][2];
#pragma unroll
    for (int i = 0; i < 4; ++i) { O2[i][0] = 0ull; O2[i][1] = 0ull; }

    for (int kt = 0; kt < St / 64; ++kt) {
        __syncthreads();
#pragma unroll
        for (int c = 0; c < 4; ++c) {
            float4 kv = *(const float4*)(kb + (size_t)(kt * 64 + lr) * HDt + lc + c * 4);
            Kst[lc + c * 4 + 0][lr] = kv.x;
            Kst[lc + c * 4 + 1][lr] = kv.y;
            Kst[lc + c * 4 + 2][lr] = kv.z;
            Kst[lc + c * 4 + 3][lr] = kv.w;
            float4 vv = *(const float4*)(vb + (size_t)(kt * 64 + lr) * HDt + lc + c * 4);
            *(float4*)&Vs[lr][lc + c * 4] = vv;
        }
        if (tid < 64) mbias[tid] = (mrow[kt * 64 + tid] - 2.0f) * 1.0e6f;
        __syncthreads();

        ull S2[4][2] = {{0ull,0ull},{0ull,0ull},{0ull,0ull},{0ull,0ull}};
#pragma unroll 4
        for (int d4 = 0; d4 < 16; ++d4) {
            const int d = d4 << 2;
            float4 k0 = *(const float4*)&Kst[d + 0][tx << 2];
            float4 k1 = *(const float4*)&Kst[d + 1][tx << 2];
            float4 k2 = *(const float4*)&Kst[d + 2][tx << 2];
            float4 k3 = *(const float4*)&Kst[d + 3][tx << 2];
            const ull kb00 = f2u(k0.x, k0.y), kb01 = f2u(k0.z, k0.w);
            const ull kb10 = f2u(k1.x, k1.y), kb11 = f2u(k1.z, k1.w);
            const ull kb20 = f2u(k2.x, k2.y), kb21 = f2u(k2.z, k2.w);
            const ull kb30 = f2u(k3.x, k3.y), kb31 = f2u(k3.z, k3.w);
#pragma unroll
            for (int i = 0; i < 4; ++i) {
                ulonglong2 qa = *(const ulonglong2*)&Qs2[(ty << 2) + i][d];
                ulonglong2 qc = *(const ulonglong2*)&Qs2[(ty << 2) + i][d + 2];
                S2[i][0] = fma2(qa.x, kb00, S2[i][0]);
                S2[i][1] = fma2(qa.x, kb01, S2[i][1]);
                S2[i][0] = fma2(qa.y, kb10, S2[i][0]);
                S2[i][1] = fma2(qa.y, kb11, S2[i][1]);
                S2[i][0] = fma2(qc.x, kb20, S2[i][0]);
                S2[i][1] = fma2(qc.x, kb21, S2[i][1]);
                S2[i][0] = fma2(qc.y, kb30, S2[i][0]);
                S2[i][1] = fma2(qc.y, kb31, S2[i][1]);
            }
        }

        const float bm0 = mbias[(tx << 2) + 0];
        const float bm1 = mbias[(tx << 2) + 1];
        const float bm2 = mbias[(tx << 2) + 2];
        const float bm3 = mbias[(tx << 2) + 3];
#pragma unroll
        for (int i = 0; i < 4; ++i) {
            float2 s01 = u2f(S2[i][0]);
            float2 s23 = u2f(S2[i][1]);
            float s0 = s01.x + bm0, s1 = s01.y + bm1;
            float s2 = s23.x + bm2, s3 = s23.y + bm3;
            float mx = fmaxf(fmaxf(s0, s1), fmaxf(s2, s3));
#pragma unroll
            for (int off = 8; off > 0; off >>= 1)
                mx = fmaxf(mx, __shfl_xor_sync(0xffffffffu, mx, off, 16));
            const float mnew = fmaxf(m_i[i], mx);
            const float corr = __expf(m_i[i] - mnew);
            const float p0 = __expf(s0 - mnew), p1 = __expf(s1 - mnew);
            const float p2 = __expf(s2 - mnew), p3 = __expf(s3 - mnew);
            float rs = p0 + p1 + p2 + p3;
#pragma unroll
            for (int off = 8; off > 0; off >>= 1)
                rs += __shfl_xor_sync(0xffffffffu, rs, off, 16);
            l_i[i] = l_i[i] * corr + rs;
            m_i[i] = mnew;
            const ull cd = f2u(corr, corr);
            O2[i][0] = mul2(O2[i][0], cd);
            O2[i][1] = mul2(O2[i][1], cd);
            sts_dup(&Ps2[(ty << 2) + i][(tx << 2) + 0], p0);
            sts_dup(&Ps2[(ty << 2) + i][(tx << 2) + 1], p1);
            sts_dup(&Ps2[(ty << 2) + i][(tx << 2) + 2], p2);
            sts_dup(&Ps2[(ty << 2) + i][(tx << 2) + 3], p3);
        }
        __syncthreads();

#pragma unroll 8
        for (int kk = 0; kk < 64; ++kk) {
            float4 v = *(const float4*)&Vs[kk][tx << 2];
            const ull vb0 = f2u(v.x, v.y), vb1 = f2u(v.z, v.w);
#pragma unroll
            for (int i = 0; i < 4; ++i) {
                const ull pd = Ps2[(ty << 2) + i][kk];
                O2[i][0] = fma2(pd, vb0, O2[i][0]);
                O2[i][1] = fma2(pd, vb1, O2[i][1]);
            }
        }
    }

    // Normalize and write out: out[b, s, h*64 + d]
#pragma unroll
    for (int i = 0; i < 4; ++i) {
        const float inv = 1.0f / l_i[i];
        const ull id = f2u(inv, inv);
        float2 o0 = u2f(mul2(O2[i][0], id));
        float2 o1 = u2f(mul2(O2[i][1], id));
        const int s = qt * 64 + (ty << 2) + i;
        float4 o = make_float4(o0.x, o0.y, o1.x, o1.y);
        *(float4*)(out + ((size_t)(b * St + s) * HIDt) + h * HDt + (tx << 2)) = o;
    }
}

extern "C" void kernel_launch(void* const* d_in, const int* in_sizes, int n_in,
                              void* d_out, int out_size)
{
    const float* X    = (const float*)d_in[0];
    const float* mask = (const float*)d_in[1];
    const float* Wq   = (const float*)d_in[2];
    const float* bq   = (const float*)d_in[3];
    const float* Wk   = (const float*)d_in[4];
    const float* bk   = (const float*)d_in[5];
    const float* Wv   = (const float*)d_in[6];
    const float* bv   = (const float*)d_in[7];
    float* out = (float*)d_out;

    cudaFuncSetAttribute(attn_kernel, cudaFuncAttributeMaxDynamicSharedMemorySize, ATTN_SMEM);

    dim3 g1(HIDt / 128, (Bt * St) / 128, 3);
    qkv_gemm<<<g1, 256>>>(X, Wq, bq, Wk, bk, Wv, bv);

    dim3 g2(St / 64, NHt, Bt);
    attn_kernel<<<g2, 256, ATTN_SMEM>>>(mask, out);
}

// round 4
// speedup vs baseline: 4.5639x; 4.5639x over previous
#include <cuda_runtime.h>
#include <cuda_bf16.h>
#include <cstdint>

typedef unsigned long long ull;

#define Bt   4
#define St   1024
#define HIDt 1024
#define NHt  16
#define HDt  64
#define LOG2E 1.4426950408889634f
#define NELEM (Bt * NHt * St * HDt)

// bf16 hi/lo split scratch for Q (pre-scaled by 0.125), K, V in [B,NH,S,HD]
__device__ __nv_bfloat16 g_qh[NELEM], g_ql[NELEM];
__device__ __nv_bfloat16 g_kh[NELEM], g_kl[NELEM];
__device__ __nv_bfloat16 g_vh[NELEM], g_vl[NELEM];

// ---------------- helpers ----------------
__device__ __forceinline__ uint32_t cvta_s(const void* p) {
    return (uint32_t)__cvta_generic_to_shared(p);
}
__device__ __forceinline__ void ldsm4(uint32_t* r, uint32_t a) {
    asm volatile("ldmatrix.sync.aligned.m8n8.x4.shared.b16 {%0,%1,%2,%3},[%4];"
        : "=r"(r[0]), "=r"(r[1]), "=r"(r[2]), "=r"(r[3]) : "r"(a));
}
__device__ __forceinline__ void ldsm4t(uint32_t* r, uint32_t a) {
    asm volatile("ldmatrix.sync.aligned.m8n8.x4.trans.shared.b16 {%0,%1,%2,%3},[%4];"
        : "=r"(r[0]), "=r"(r[1]), "=r"(r[2]), "=r"(r[3]) : "r"(a));
}
__device__ __forceinline__ void mma_bf(float* c, const uint32_t* a, const uint32_t* b) {
    asm volatile("mma.sync.aligned.m16n8k16.row.col.f32.bf16.bf16.f32 "
        "{%0,%1,%2,%3},{%4,%5,%6,%7},{%8,%9},{%0,%1,%2,%3};"
        : "+f"(c[0]), "+f"(c[1]), "+f"(c[2]), "+f"(c[3])
        : "r"(a[0]), "r"(a[1]), "r"(a[2]), "r"(a[3]), "r"(b[0]), "r"(b[1]));
}
// pack two floats to bf16x2; e0 -> low half (element k=2c)
__device__ __forceinline__ uint32_t pbf2(float e0, float e1) {
    uint32_t r; asm("cvt.rn.bf16x2.f32 %0, %1, %2;" : "=r"(r) : "f"(e1), "f"(e0)); return r;
}
__device__ __forceinline__ void splitf(float x, float& h, float& l) {
    h = __bfloat162float(__float2bfloat16(x));
    l = x - h;
}
__device__ __forceinline__ float ex2(float x) {
    float y; asm("ex2.approx.ftz.f32 %0, %1;" : "=f"(y) : "f"(x)); return y;
}

// ================= QKV projection GEMM (bf16-split mma) ====================
// block tile 128(M) x 128(N), K-step 16; 8 warps: 4(M) x 2(N), warp 32x64.
__global__ __launch_bounds__(256)
void qkv_gemm(const float* __restrict__ X,
              const float* __restrict__ Wq, const float* __restrict__ bq,
              const float* __restrict__ Wk, const float* __restrict__ bk,
              const float* __restrict__ Wv, const float* __restrict__ bv)
{
    __shared__ __align__(16) __nv_bfloat16 Ah[128][24], Al[128][24];
    __shared__ __align__(16) __nv_bfloat16 Bh[128][24], Bl[128][24];

    const int tid = threadIdx.x;
    const int bx = blockIdx.x, by = blockIdx.y, mz = blockIdx.z;
    const float* W    = (mz == 0) ? Wq : (mz == 1) ? Wk : Wv;
    const float* bias = (mz == 0) ? bq : (mz == 1) ? bk : bv;
    __nv_bfloat16* dh = (mz == 0) ? g_qh : (mz == 1) ? g_kh : g_vh;
    __nv_bfloat16* dl = (mz == 0) ? g_ql : (mz == 1) ? g_kl : g_vl;

    const float* Ap = X + (size_t)(by * 128) * HIDt;
    const float* Wp = W + (size_t)(bx * 128) * HIDt;

    const int lrow = tid >> 1;
    const int lcol = (tid & 1) * 8;
    const int wid = tid >> 5, lane = tid & 31;
    const int wm = (wid & 3) * 32;
    const int wn = (wid >> 2) * 64;

    float acc[2][8][4];
#pragma unroll
    for (int i = 0; i < 2; ++i)
#pragma unroll
        for (int j = 0; j < 8; ++j)
#pragma unroll
            for (int k = 0; k < 4; ++k) acc[i][j][k] = 0.f;

    float4 ar[2], wr[2];
#pragma unroll
    for (int c = 0; c < 2; ++c) {
        ar[c] = *(const float4*)(Ap + (size_t)lrow * HIDt + lcol + c * 4);
        wr[c] = *(const float4*)(Wp + (size_t)lrow * HIDt + lcol + c * 4);
    }

    for (int kt = 0; kt < HIDt / 16; ++kt) {
        __syncthreads();
#pragma unroll
        for (int c = 0; c < 2; ++c) {
            const float* af = (const float*)&ar[c];
            const float* wf = (const float*)&wr[c];
#pragma unroll
            for (int e = 0; e < 4; e += 2) {
                float h0, l0, h1, l1;
                splitf(af[e], h0, l0); splitf(af[e + 1], h1, l1);
                *(uint32_t*)&Ah[lrow][lcol + c * 4 + e] = pbf2(h0, h1);
                *(uint32_t*)&Al[lrow][lcol + c * 4 + e] = pbf2(l0, l1);
                splitf(wf[e], h0, l0); splitf(wf[e + 1], h1, l1);
                *(uint32_t*)&Bh[lrow][lcol + c * 4 + e] = pbf2(h0, h1);
                *(uint32_t*)&Bl[lrow][lcol + c * 4 + e] = pbf2(l0, l1);
            }
        }
        __syncthreads();
        if (kt + 1 < HIDt / 16) {
            const int k0 = (kt + 1) * 16;
#pragma unroll
            for (int c = 0; c < 2; ++c) {
                ar[c] = *(const float4*)(Ap + (size_t)lrow * HIDt + k0 + lcol + c * 4);
                wr[c] = *(const float4*)(Wp + (size_t)lrow * HIDt + k0 + lcol + c * 4);
            }
        }
        uint32_t a_h[2][4], a_l[2][4];
#pragma unroll
        for (int mi = 0; mi < 2; ++mi) {
            const int arow = wm + mi * 16 + (lane & 15);
            const int acol = (lane >> 4) * 8;
            ldsm4(a_h[mi], cvta_s(&Ah[arow][acol]));
            ldsm4(a_l[mi], cvta_s(&Al[arow][acol]));
        }
#pragma unroll
        for (int nb = 0; nb < 4; ++nb) {
            const int brow = wn + nb * 16 + (lane & 15);
            const int bcol = (lane >> 4) * 8;
            uint32_t bh4[4], bl4[4];
            ldsm4(bh4, cvta_s(&Bh[brow][bcol]));
            ldsm4(bl4, cvta_s(&Bl[brow][bcol]));
            uint32_t b0h[2] = {bh4[0], bh4[2]}, b1h[2] = {bh4[1], bh4[3]};
            uint32_t b0l[2] = {bl4[0], bl4[2]}, b1l[2] = {bl4[1], bl4[3]};
#pragma unroll
            for (int mi = 0; mi < 2; ++mi) {
                float* c0 = acc[mi][nb * 2];
                float* c1 = acc[mi][nb * 2 + 1];
                mma_bf(c0, a_h[mi], b0h); mma_bf(c0, a_l[mi], b0h); mma_bf(c0, a_h[mi], b0l);
                mma_bf(c1, a_h[mi], b1h); mma_bf(c1, a_l[mi], b1h); mma_bf(c1, a_h[mi], b1l);
            }
        }
    }

    // epilogue: add bias, (0.125 scale for Q), split to bf16 hi/lo, scatter [B,NH,S,HD]
    const float qs = (mz == 0) ? 0.125f : 1.0f;
#pragma unroll
    for (int mi = 0; mi < 2; ++mi) {
#pragma unroll
        for (int nb2 = 0; nb2 < 8; ++nb2) {
            const int n = bx * 128 + wn + nb2 * 8 + (lane & 3) * 2;
            const float2 bv2 = *(const float2*)(bias + n);
            const int hh = n >> 6, d = n & 63;
#pragma unroll
            for (int rr = 0; rr < 2; ++rr) {
                const int m = by * 128 + wm + mi * 16 + (lane >> 2) + rr * 8;
                const int b = m >> 10, s = m & 1023;
                const float x0 = (acc[mi][nb2][rr * 2 + 0] + bv2.x) * qs;
                const float x1 = (acc[mi][nb2][rr * 2 + 1] + bv2.y) * qs;
                float h0, l0, h1, l1;
                splitf(x0, h0, l0); splitf(x1, h1, l1);
                const size_t off = (((size_t)(b * NHt + hh)) * St + s) * HDt + d;
                *(uint32_t*)&dh[off] = pbf2(h0, h1);
                *(uint32_t*)&dl[off] = pbf2(l0, l1);
            }
        }
    }
}

// ================= Flash attention (bf16-split mma, FA2 layout) =============
#define ASMEM (6 * 64 * 72 * 2 + 256)

__global__ __launch_bounds__(128)
void attn_mma(const float* __restrict__ mask, float* __restrict__ out)
{
    extern __shared__ __align__(16) char sm[];
    __nv_bfloat16 (*Qh)[72] = (__nv_bfloat16(*)[72])(sm);
    __nv_bfloat16 (*Ql)[72] = (__nv_bfloat16(*)[72])(sm + 9216);
    __nv_bfloat16 (*Kh)[72] = (__nv_bfloat16(*)[72])(sm + 18432);
    __nv_bfloat16 (*Kl)[72] = (__nv_bfloat16(*)[72])(sm + 27648);
    __nv_bfloat16 (*Vh)[72] = (__nv_bfloat16(*)[72])(sm + 36864);
    __nv_bfloat16 (*Vl)[72] = (__nv_bfloat16(*)[72])(sm + 46080);
    float* mb = (float*)(sm + 55296);

    const int tid = threadIdx.x;
    const int lane = tid & 31, wid = tid >> 5;
    const int qt = blockIdx.x, h = blockIdx.y, b = blockIdx.z;

    const size_t bh = ((size_t)(b * NHt + h)) * St * HDt;
    const __nv_bfloat16* qhp = g_qh + bh + (size_t)qt * 64 * HDt;
    const __nv_bfloat16* qlp = g_ql + bh + (size_t)qt * 64 * HDt;
    const __nv_bfloat16* khp = g_kh + bh;
    const __nv_bfloat16* klp = g_kl + bh;
    const __nv_bfloat16* vhp = g_vh + bh;
    const __nv_bfloat16* vlp = g_vl + bh;
    const float* mrow = mask + (size_t)b * St;

    for (int i = tid; i < 512; i += 128) {
        const int r = i >> 3, c = (i & 7) * 8;
        *(uint4*)&Qh[r][c] = *(const uint4*)(qhp + r * 64 + c);
        *(uint4*)&Ql[r][c] = *(const uint4*)(qlp + r * 64 + c);
    }

    float o[8][4];
#pragma unroll
    for (int j = 0; j < 8; ++j)
#pragma unroll
        for (int k = 0; k < 4; ++k) o[j][k] = 0.f;
    float m0 = -1e30f, m1 = -1e30f, l0 = 0.f, l1 = 0.f;

    for (int kt = 0; kt < 16; ++kt) {
        __syncthreads();
        const size_t ko = (size_t)kt * 64 * HDt;
        for (int i = tid; i < 512; i += 128) {
            const int r = i >> 3, c = (i & 7) * 8;
            *(uint4*)&Kh[r][c] = *(const uint4*)(khp + ko + r * 64 + c);
            *(uint4*)&Kl[r][c] = *(const uint4*)(klp + ko + r * 64 + c);
            *(uint4*)&Vh[r][c] = *(const uint4*)(vhp + ko + r * 64 + c);
            *(uint4*)&Vl[r][c] = *(const uint4*)(vlp + ko + r * 64 + c);
        }
        // NATURAL-domain mask bias, exactly matching the reference's fp32 add.
        if (tid < 64) mb[tid] = (mrow[kt * 64 + tid] - 2.0f) * 1.0e6f;
        __syncthreads();

        // ---- S = Q * K^T (natural domain; 4-term split for accuracy) ----
        float s[8][4];
#pragma unroll
        for (int j = 0; j < 8; ++j)
#pragma unroll
            for (int k = 0; k < 4; ++k) s[j][k] = 0.f;

#pragma unroll
        for (int kb = 0; kb < 4; ++kb) {
            uint32_t aqh[4], aql[4];
            const int qrow = wid * 16 + (lane & 15);
            const int qcol = kb * 16 + (lane >> 4) * 8;
            ldsm4(aqh, cvta_s(&Qh[qrow][qcol]));
            ldsm4(aql, cvta_s(&Ql[qrow][qcol]));
#pragma unroll
            for (int nb = 0; nb < 4; ++nb) {
                const int krow = nb * 16 + (lane & 15);
                uint32_t bh4[4], bl4[4];
                ldsm4(bh4, cvta_s(&Kh[krow][qcol]));
                ldsm4(bl4, cvta_s(&Kl[krow][qcol]));
                uint32_t b0h[2] = {bh4[0], bh4[2]}, b1h[2] = {bh4[1], bh4[3]};
                uint32_t b0l[2] = {bl4[0], bl4[2]}, b1l[2] = {bl4[1], bl4[3]};
                float* s0 = s[nb * 2];
                float* s1 = s[nb * 2 + 1];
                mma_bf(s0, aqh, b0h); mma_bf(s0, aql, b0h);
                mma_bf(s0, aqh, b0l); mma_bf(s0, aql, b0l);
                mma_bf(s1, aqh, b1h); mma_bf(s1, aql, b1h);
                mma_bf(s1, aqh, b1l); mma_bf(s1, aql, b1l);
            }
        }

        // ---- mask bias + online softmax (max in natural, exp via ex2) ----
        float rmax0 = -1e30f, rmax1 = -1e30f;
#pragma unroll
        for (int j = 0; j < 8; ++j) {
            const float bm0 = mb[j * 8 + (lane & 3) * 2];
            const float bm1 = mb[j * 8 + (lane & 3) * 2 + 1];
            s[j][0] += bm0; s[j][1] += bm1; s[j][2] += bm0; s[j][3] += bm1;
            rmax0 = fmaxf(rmax0, fmaxf(s[j][0], s[j][1]));
            rmax1 = fmaxf(rmax1, fmaxf(s[j][2], s[j][3]));
        }
        rmax0 = fmaxf(rmax0, __shfl_xor_sync(0xffffffffu, rmax0, 1));
        rmax0 = fmaxf(rmax0, __shfl_xor_sync(0xffffffffu, rmax0, 2));
        rmax1 = fmaxf(rmax1, __shfl_xor_sync(0xffffffffu, rmax1, 1));
        rmax1 = fmaxf(rmax1, __shfl_xor_sync(0xffffffffu, rmax1, 2));
        const float mn0 = fmaxf(m0, rmax0), mn1 = fmaxf(m1, rmax1);
        const float c0 = ex2((m0 - mn0) * LOG2E), c1 = ex2((m1 - mn1) * LOG2E);
        float rs0 = 0.f, rs1 = 0.f;

        uint32_t pah[4][4], pal[4][4];
#pragma unroll
        for (int j2 = 0; j2 < 4; ++j2) {
#pragma unroll
            for (int q = 0; q < 2; ++q) {
                const int j = j2 * 2 + q;
                const float p0 = ex2((s[j][0] - mn0) * LOG2E);
                const float p1 = ex2((s[j][1] - mn0) * LOG2E);
                const float p2 = ex2((s[j][2] - mn1) * LOG2E);
                const float p3 = ex2((s[j][3] - mn1) * LOG2E);
                rs0 += p0 + p1; rs1 += p2 + p3;
                float h0, e0, h1, e1, h2, e2, h3, e3;
                splitf(p0, h0, e0); splitf(p1, h1, e1);
                splitf(p2, h2, e2); splitf(p3, h3, e3);
                pah[j2][q * 2 + 0] = pbf2(h0, h1);
                pah[j2][q * 2 + 1] = pbf2(h2, h3);
                pal[j2][q * 2 + 0] = pbf2(e0, e1);
                pal[j2][q * 2 + 1] = pbf2(e2, e3);
            }
        }

        rs0 += __shfl_xor_sync(0xffffffffu, rs0, 1);
        rs0 += __shfl_xor_sync(0xffffffffu, rs0, 2);
        rs1 += __shfl_xor_sync(0xffffffffu, rs1, 1);
        rs1 += __shfl_xor_sync(0xffffffffu, rs1, 2);
        l0 = l0 * c0 + rs0; l1 = l1 * c1 + rs1;
        m0 = mn0; m1 = mn1;
#pragma unroll
        for (int j = 0; j < 8; ++j) {
            o[j][0] *= c0; o[j][1] *= c0; o[j][2] *= c1; o[j][3] *= c1;
        }

        // ---- O += P * V (3-term split) ----
        const int grp = lane >> 3, li = lane & 7;
#pragma unroll
        for (int j2 = 0; j2 < 4; ++j2) {
            const int vr = j2 * 16 + ((grp & 1) ? 8 : 0) + li;
#pragma unroll
            for (int db = 0; db < 4; ++db) {
                const int vc = db * 16 + ((grp >= 2) ? 8 : 0);
                uint32_t vh4[4], vl4[4];
                ldsm4t(vh4, cvta_s(&Vh[vr][vc]));
                ldsm4t(vl4, cvta_s(&Vl[vr][vc]));
                uint32_t b0h[2] = {vh4[0], vh4[1]}, b1h[2] = {vh4[2], vh4[3]};
                uint32_t b0l[2] = {vl4[0], vl4[1]}, b1l[2] = {vl4[2], vl4[3]};
                float* o0 = o[db * 2];
                float* o1 = o[db * 2 + 1];
                mma_bf(o0, pah[j2], b0h); mma_bf(o0, pal[j2], b0h); mma_bf(o0, pah[j2], b0l);
                mma_bf(o1, pah[j2], b1h); mma_bf(o1, pal[j2], b1h); mma_bf(o1, pah[j2], b1l);
            }
        }
    }

    // ---- normalize + write out[b, s, h*64 + d] ----
    const float inv0 = 1.f / l0, inv1 = 1.f / l1;
    const int r0 = qt * 64 + wid * 16 + (lane >> 2);
#pragma unroll
    for (int db2 = 0; db2 < 8; ++db2) {
        const int d = db2 * 8 + (lane & 3) * 2;
        float2 v0 = make_float2(o[db2][0] * inv0, o[db2][1] * inv0);
        float2 v1 = make_float2(o[db2][2] * inv1, o[db2][3] * inv1);
        *(float2*)(out + (size_t)(b * St + r0) * HIDt + h * 64 + d) = v0;
        *(float2*)(out + (size_t)(b * St + r0 + 8) * HIDt + h * 64 + d) = v1;
    }
}

extern "C" void kernel_launch(void* const* d_in, const int* in_sizes, int n_in,
                              void* d_out, int out_size)
{
    const float* X    = (const float*)d_in[0];
    const float* mask = (const float*)d_in[1];
    const float* Wq   = (const float*)d_in[2];
    const float* bq   = (const float*)d_in[3];
    const float* Wk   = (const float*)d_in[4];
    const float* bk   = (const float*)d_in[5];
    const float* Wv   = (const float*)d_in[6];
    const float* bv   = (const float*)d_in[7];
    float* out = (float*)d_out;

    cudaFuncSetAttribute(attn_mma, cudaFuncAttributeMaxDynamicSharedMemorySize, ASMEM);

    dim3 g1(HIDt / 128, (Bt * St) / 128, 3);
    qkv_gemm<<<g1, 256>>>(X, Wq, bq, Wk, bk, Wv, bv);

    dim3 g2(St / 64, NHt, Bt);
    attn_mma<<<g2, 128, ASMEM>>>(mask, out);
}